// round 1
// baseline (speedup 1.0000x reference)
#include <cuda_runtime.h>
#include <cuda_bf16.h>
#include <cstdint>

// Problem constants (from reference setup_inputs)
#define BATCH  4096
#define CWDIM  1024
#define CODES  128     // C = cw_dim / dim_embedding
#define BOOK   256     // K
#define DEMB   8       // D

// Scratch for argmin indices (allocation-free: static device global)
__device__ unsigned char g_idx[BATCH * CODES];

// ---------------------------------------------------------------------------
// Kernel 1: per (b, c) argmin over K=256 codes; writes cw_embed + index.
// grid = (BATCH/256, CODES), block = 256 threads. One c per block.
// score(k) = 0.5*||c_k||^2 - x . c_k   (same argmin as full distance)
// ---------------------------------------------------------------------------
__global__ void __launch_bounds__(256)
vq_argmin_kernel(const float* __restrict__ x,
                 const float* __restrict__ cb,
                 float* __restrict__ cw_embed)
{
    __shared__ float4 s_cb[BOOK * 2];   // codebook[c]: 256 rows x 8 floats
    __shared__ float  s_c2h[BOOK];      // 0.5 * ||c_k||^2

    const int c = blockIdx.y;
    const int t = threadIdx.x;

    // Stage codebook[c] into smem (512 float4 by 256 threads)
    const float4* cb4 = reinterpret_cast<const float4*>(cb + (size_t)c * BOOK * DEMB);
    float4 r0 = cb4[t * 2 + 0];
    float4 r1 = cb4[t * 2 + 1];
    s_cb[t * 2 + 0] = r0;
    s_cb[t * 2 + 1] = r1;
    s_c2h[t] = 0.5f * (r0.x * r0.x + r0.y * r0.y + r0.z * r0.z + r0.w * r0.w +
                       r1.x * r1.x + r1.y * r1.y + r1.z * r1.z + r1.w * r1.w);
    __syncthreads();

    const int b = blockIdx.x * 256 + t;

    // Load this thread's x slice: x[b, c*8 .. c*8+7]
    const float4* xp = reinterpret_cast<const float4*>(x + (size_t)b * CWDIM + c * DEMB);
    float4 x0 = xp[0];
    float4 x1 = xp[1];
    // Negate once so the inner loop is pure FMA: acc = c2h + sum(-x * c)
    const float xn0 = -x0.x, xn1 = -x0.y, xn2 = -x0.z, xn3 = -x0.w;
    const float xn4 = -x1.x, xn5 = -x1.y, xn6 = -x1.z, xn7 = -x1.w;

    float best = 3.4e38f;
    int   bi   = 0;

    #pragma unroll 4
    for (int k = 0; k < BOOK; ++k) {
        float4 c0 = s_cb[2 * k + 0];
        float4 c1 = s_cb[2 * k + 1];
        float s = s_c2h[k];
        s = fmaf(xn0, c0.x, s);
        s = fmaf(xn1, c0.y, s);
        s = fmaf(xn2, c0.z, s);
        s = fmaf(xn3, c0.w, s);
        s = fmaf(xn4, c1.x, s);
        s = fmaf(xn5, c1.y, s);
        s = fmaf(xn6, c1.z, s);
        s = fmaf(xn7, c1.w, s);
        // strict < keeps the FIRST minimum (matches jnp.argmin tie-break)
        if (s < best) { best = s; bi = k; }
    }

    g_idx[(size_t)b * CODES + c] = (unsigned char)bi;

    // cw_embed[b, c*8 .. c*8+7] = codebook[c, bi, :]
    float4* out4 = reinterpret_cast<float4*>(cw_embed + (size_t)b * CWDIM + c * DEMB);
    out4[0] = s_cb[2 * bi + 0];
    out4[1] = s_cb[2 * bi + 1];
}

// ---------------------------------------------------------------------------
// Kernel 2: one_hot fill. One float4 (4 k-slots) per thread, fully coalesced.
// Layout: one_hot[b][c][k]; linear float4 index i -> k4 = i & 63,
// bc = i >> 6 (b*CODES + c).
// ---------------------------------------------------------------------------
__global__ void __launch_bounds__(256)
vq_onehot_kernel(float* __restrict__ oh)
{
    const size_t i = (size_t)blockIdx.x * blockDim.x + threadIdx.x;  // float4 index
    const unsigned kbase = ((unsigned)i & 63u) * 4u;
    const size_t   bc    = i >> 6;

    const unsigned idx = g_idx[bc];

    float4 v;
    v.x = (idx == kbase + 0u) ? 1.0f : 0.0f;
    v.y = (idx == kbase + 1u) ? 1.0f : 0.0f;
    v.z = (idx == kbase + 2u) ? 1.0f : 0.0f;
    v.w = (idx == kbase + 3u) ? 1.0f : 0.0f;

    reinterpret_cast<float4*>(oh)[i] = v;
}

// ---------------------------------------------------------------------------
extern "C" void kernel_launch(void* const* d_in, const int* in_sizes, int n_in,
                              void* d_out, int out_size)
{
    const float* x  = (const float*)d_in[0];   // [4096, 1024]
    const float* cb = (const float*)d_in[1];   // [128, 256, 8]

    float* cw_embed = (float*)d_out;                               // [4096, 1024]
    float* one_hot  = (float*)d_out + (size_t)BATCH * CWDIM;       // [4096, 128, 256]

    {
        dim3 grid(BATCH / 256, CODES);
        vq_argmin_kernel<<<grid, 256>>>(x, cb, cw_embed);
    }
    {
        const size_t n4 = (size_t)BATCH * CODES * BOOK / 4;  // 33,554,432
        vq_onehot_kernel<<<(unsigned)(n4 / 256), 256>>>(one_hot);
    }
}

// round 2
// speedup vs baseline: 1.6042x; 1.6042x over previous
#include <cuda_runtime.h>
#include <cuda_bf16.h>
#include <cstdint>

// Problem constants (from reference setup_inputs)
#define BATCH  4096
#define CWDIM  1024
#define CODES  128     // C
#define BOOK   256     // K
#define DEMB   8       // D

// ---------------------------------------------------------------------------
// Fused kernel: per (b, c) argmin over K=256 codes, then the block writes
//   - cw_embed[b, c*8:(c+1)*8]
//   - one_hot[b, c, :] for its 256 b-rows (fully coalesced, zero + hot patch)
// grid = (BATCH/256, CODES), block = 256 threads, one c per block.
// score(k) = 0.5*||c_k||^2 - x . c_k   (same argmin as full distance)
// ---------------------------------------------------------------------------
__global__ void __launch_bounds__(256)
vq_fused_kernel(const float* __restrict__ x,
                const float* __restrict__ cb,
                float* __restrict__ cw_embed,
                float* __restrict__ one_hot)
{
    __shared__ float4        s_cb[BOOK * 2];   // codebook[c]: 256 rows x 8 floats
    __shared__ float         s_c2h[BOOK];      // 0.5 * ||c_k||^2
    __shared__ unsigned char s_idx[256];       // argmin index per b-row of this block

    const int c = blockIdx.y;
    const int t = threadIdx.x;

    // ---- Stage codebook[c] into smem (512 float4 by 256 threads) ----
    const float4* cb4 = reinterpret_cast<const float4*>(cb + (size_t)c * BOOK * DEMB);
    float4 r0 = cb4[t * 2 + 0];
    float4 r1 = cb4[t * 2 + 1];
    s_cb[t * 2 + 0] = r0;
    s_cb[t * 2 + 1] = r1;
    s_c2h[t] = 0.5f * (r0.x * r0.x + r0.y * r0.y + r0.z * r0.z + r0.w * r0.w +
                       r1.x * r1.x + r1.y * r1.y + r1.z * r1.z + r1.w * r1.w);
    __syncthreads();

    const int b = blockIdx.x * 256 + t;

    // ---- Argmin over K=256 ----
    const float4* xp = reinterpret_cast<const float4*>(x + (size_t)b * CWDIM + c * DEMB);
    float4 x0 = xp[0];
    float4 x1 = xp[1];
    const float xn0 = -x0.x, xn1 = -x0.y, xn2 = -x0.z, xn3 = -x0.w;
    const float xn4 = -x1.x, xn5 = -x1.y, xn6 = -x1.z, xn7 = -x1.w;

    float best = 3.4e38f;
    int   bi   = 0;

    #pragma unroll 4
    for (int k = 0; k < BOOK; ++k) {
        float4 c0 = s_cb[2 * k + 0];
        float4 c1 = s_cb[2 * k + 1];
        float s = s_c2h[k];
        s = fmaf(xn0, c0.x, s);
        s = fmaf(xn1, c0.y, s);
        s = fmaf(xn2, c0.z, s);
        s = fmaf(xn3, c0.w, s);
        s = fmaf(xn4, c1.x, s);
        s = fmaf(xn5, c1.y, s);
        s = fmaf(xn6, c1.z, s);
        s = fmaf(xn7, c1.w, s);
        // strict < keeps the FIRST minimum (matches jnp.argmin tie-break)
        if (s < best) { best = s; bi = k; }
    }

    s_idx[t] = (unsigned char)bi;

    // ---- cw_embed[b, c*8 .. c*8+7] = codebook[c, bi, :] ----
    float4* out4 = reinterpret_cast<float4*>(cw_embed + (size_t)b * CWDIM + c * DEMB);
    out4[0] = s_cb[2 * bi + 0];
    out4[1] = s_cb[2 * bi + 1];

    __syncthreads();

    // ---- one_hot fill: this block owns rows bc = (b0 + r)*CODES + c, r=0..255
    // Each row is 256 floats = 64 float4 = 1KB, written by 64 threads.
    // 256 threads cover 4 rows per iteration -> 64 iterations.
    const int off  = t & 63;   // float4 slot within row (covers k = off*4 .. off*4+3)
    const int rsub = t >> 6;   // which of the 4 rows this iteration

    const int b0 = blockIdx.x * 256;
    // float4 base address for (row = b0 + rsub, code c), slot off
    float4* oh4 = reinterpret_cast<float4*>(one_hot)
                + (size_t)(b0 + rsub) * (CODES * BOOK / 4)
                + (size_t)c * (BOOK / 4)
                + off;
    const size_t step4 = (size_t)4 * (CODES * BOOK / 4);   // 4 b-rows per iteration

    const float4 zero = make_float4(0.f, 0.f, 0.f, 0.f);

    #pragma unroll 8
    for (int it = 0; it < 64; ++it) {
        const unsigned idx = s_idx[it * 4 + rsub];
        float4 v = zero;
        if ((idx >> 2) == (unsigned)off) {
            const unsigned l = idx & 3u;
            v.x = (l == 0u) ? 1.0f : 0.0f;
            v.y = (l == 1u) ? 1.0f : 0.0f;
            v.z = (l == 2u) ? 1.0f : 0.0f;
            v.w = (l == 3u) ? 1.0f : 0.0f;
        }
        *oh4 = v;
        oh4 += step4;
    }
}

// ---------------------------------------------------------------------------
extern "C" void kernel_launch(void* const* d_in, const int* in_sizes, int n_in,
                              void* d_out, int out_size)
{
    const float* x  = (const float*)d_in[0];   // [4096, 1024]
    const float* cb = (const float*)d_in[1];   // [128, 256, 8]

    float* cw_embed = (float*)d_out;                               // [4096, 1024]
    float* one_hot  = (float*)d_out + (size_t)BATCH * CWDIM;       // [4096, 128, 256]

    dim3 grid(BATCH / 256, CODES);
    vq_fused_kernel<<<grid, 256>>>(x, cb, cw_embed, one_hot);
}